// round 1
// baseline (speedup 1.0000x reference)
#include <cuda_runtime.h>
#include <cuda_bf16.h>
#include <cstdint>

#define MDIM 16384
#define NDIM 2048
#define KDIM 2048

#define BM 128
#define BN 128
#define BK 32
#define LDSX 40                         // padded smem row stride (elements)
#define TILE_BYTES (BM * LDSX * 2)      // 10240 B per tile
#define STAGE_BYTES (4 * TILE_BYTES)    // A_hi, A_lo, B_hi, B_lo
#define SMEM_TOTAL (2 * STAGE_BYTES)    // 81920 B, double buffered

// Split-precision scratch (device globals: allocation-free per harness rules)
__device__ __nv_bfloat16 g_xhi[(size_t)MDIM * KDIM];
__device__ __nv_bfloat16 g_xlo[(size_t)MDIM * KDIM];
__device__ __nv_bfloat16 g_whi[(size_t)NDIM * KDIM];
__device__ __nv_bfloat16 g_wlo[(size_t)NDIM * KDIM];

__device__ __forceinline__ void split1(float v, __nv_bfloat16& h, __nv_bfloat16& l) {
    h = __float2bfloat16(v);
    l = __float2bfloat16(v - __bfloat162float(h));
}

__global__ void split_x_kernel(const float4* __restrict__ x, int n4) {
    int i = blockIdx.x * blockDim.x + threadIdx.x;
    if (i >= n4) return;
    float4 v = x[i];
    __nv_bfloat16 h0, h1, h2, h3, l0, l1, l2, l3;
    split1(v.x, h0, l0); split1(v.y, h1, l1);
    split1(v.z, h2, l2); split1(v.w, h3, l3);
    __nv_bfloat162* ph = reinterpret_cast<__nv_bfloat162*>(g_xhi);
    __nv_bfloat162* pl = reinterpret_cast<__nv_bfloat162*>(g_xlo);
    __nv_bfloat162 a, b;
    a.x = h0; a.y = h1; b.x = h2; b.y = h3;
    ph[2 * i] = a; ph[2 * i + 1] = b;
    a.x = l0; a.y = l1; b.x = l2; b.y = l3;
    pl[2 * i] = a; pl[2 * i + 1] = b;
}

__global__ void split_w_kernel(const float4* __restrict__ w,
                               const float4* __restrict__ m, int n4) {
    int i = blockIdx.x * blockDim.x + threadIdx.x;
    if (i >= n4) return;
    float4 wv = w[i];
    float4 mv = m[i];
    float p0 = wv.x * mv.x, p1 = wv.y * mv.y, p2 = wv.z * mv.z, p3 = wv.w * mv.w;
    __nv_bfloat16 h0, h1, h2, h3, l0, l1, l2, l3;
    split1(p0, h0, l0); split1(p1, h1, l1);
    split1(p2, h2, l2); split1(p3, h3, l3);
    __nv_bfloat162* ph = reinterpret_cast<__nv_bfloat162*>(g_whi);
    __nv_bfloat162* pl = reinterpret_cast<__nv_bfloat162*>(g_wlo);
    __nv_bfloat162 a, b;
    a.x = h0; a.y = h1; b.x = h2; b.y = h3;
    ph[2 * i] = a; ph[2 * i + 1] = b;
    a.x = l0; a.y = l1; b.x = l2; b.y = l3;
    pl[2 * i] = a; pl[2 * i + 1] = b;
}

#define CP_ASYNC16(dst_u32, src_ptr) \
    asm volatile("cp.async.cg.shared.global [%0], [%1], 16;\n" :: "r"(dst_u32), "l"(src_ptr))
#define CP_COMMIT() asm volatile("cp.async.commit_group;\n" ::: "memory")
#define CP_WAIT0()  asm volatile("cp.async.wait_group 0;\n" ::: "memory")

#define LDSM_X4(r0, r1, r2, r3, addr) \
    asm volatile("ldmatrix.sync.aligned.m8n8.x4.shared.b16 {%0,%1,%2,%3}, [%4];" \
                 : "=r"(r0), "=r"(r1), "=r"(r2), "=r"(r3) : "r"(addr))

#define MMA16816(d, a, b0, b1) \
    asm volatile("mma.sync.aligned.m16n8k16.row.col.f32.bf16.bf16.f32 " \
                 "{%0,%1,%2,%3}, {%4,%5,%6,%7}, {%8,%9}, {%0,%1,%2,%3};" \
                 : "+f"(d[0]), "+f"(d[1]), "+f"(d[2]), "+f"(d[3]) \
                 : "r"(a[0]), "r"(a[1]), "r"(a[2]), "r"(a[3]), "r"(b0), "r"(b1))

__global__ __launch_bounds__(256)
void gemm_bf16x3_kernel(float* __restrict__ out, const float* __restrict__ bias) {
    extern __shared__ __align__(16) unsigned char smem_raw[];
    const uint32_t smem_base = (uint32_t)__cvta_generic_to_shared(smem_raw);

    const int tid = threadIdx.x;
    const int lane = tid & 31;
    const int warp = tid >> 5;
    const int wm0 = (warp >> 2) * 64;   // 2 warp rows * 64
    const int wn0 = (warp & 3) * 32;    // 4 warp cols * 32
    const int gm0 = blockIdx.y * BM;
    const int gn0 = blockIdx.x * BN;

    float acc[4][4][4];
    #pragma unroll
    for (int i = 0; i < 4; i++)
        #pragma unroll
        for (int j = 0; j < 4; j++)
            #pragma unroll
            for (int r = 0; r < 4; r++)
                acc[i][j][r] = 0.0f;

    // ---- smem fill: 128 rows x 32 cols bf16, 4 chunks of 8 elems per row ----
    const int fr = tid >> 2;            // 0..63, two passes of 64 rows
    const int fc = (tid & 3) * 8;       // element offset of 16B chunk

    auto load_stage = [&](int kt, int s) {
        const int k0 = kt * BK;
        const uint32_t sbase = smem_base + (uint32_t)s * STAGE_BYTES;
        #pragma unroll
        for (int p = 0; p < 2; p++) {
            const int row = fr + p * 64;
            const uint32_t d = sbase + (uint32_t)(row * LDSX + fc) * 2;
            const size_t aoff = (size_t)(gm0 + row) * KDIM + k0 + fc;
            const size_t boff = (size_t)(gn0 + row) * KDIM + k0 + fc;
            CP_ASYNC16(d + 0u * TILE_BYTES, g_xhi + aoff);
            CP_ASYNC16(d + 1u * TILE_BYTES, g_xlo + aoff);
            CP_ASYNC16(d + 2u * TILE_BYTES, g_whi + boff);
            CP_ASYNC16(d + 3u * TILE_BYTES, g_wlo + boff);
        }
        CP_COMMIT();
    };

    // ldmatrix addressing (rows within tile, col selectors per lane group)
    const int a_row = wm0 + (lane & 15);
    const int a_csel = ((lane >> 4) << 3);
    const int b_row = wn0 + (lane & 7) + ((lane >> 4) << 3);
    const int b_csel = (((lane >> 3) & 1) << 3);

    load_stage(0, 0);

    const int KT = KDIM / BK;   // 64
    for (int kt = 0; kt < KT; kt++) {
        CP_WAIT0();
        __syncthreads();
        if (kt + 1 < KT) load_stage(kt + 1, (kt + 1) & 1);

        const uint32_t sb = smem_base + (uint32_t)(kt & 1) * STAGE_BYTES;
        #pragma unroll
        for (int kk = 0; kk < 2; kk++) {
            const int k0 = kk * 16;
            uint32_t af[2][4][4];   // [hi/lo][m tile][4 regs]
            #pragma unroll
            for (int im = 0; im < 4; im++) {
                const uint32_t addr =
                    sb + (uint32_t)(((a_row + im * 16) * LDSX) + k0 + a_csel) * 2;
                LDSM_X4(af[0][im][0], af[0][im][1], af[0][im][2], af[0][im][3], addr);
                LDSM_X4(af[1][im][0], af[1][im][1], af[1][im][2], af[1][im][3],
                        addr + TILE_BYTES);
            }
            uint32_t bf[2][2][4];   // [hi/lo][n16 pair][4 regs: n8a(k0,k8), n8b(k0,k8)]
            #pragma unroll
            for (int ib = 0; ib < 2; ib++) {
                const uint32_t addr =
                    sb + 2u * TILE_BYTES +
                    (uint32_t)(((b_row + ib * 16) * LDSX) + k0 + b_csel) * 2;
                LDSM_X4(bf[0][ib][0], bf[0][ib][1], bf[0][ib][2], bf[0][ib][3], addr);
                LDSM_X4(bf[1][ib][0], bf[1][ib][1], bf[1][ib][2], bf[1][ib][3],
                        addr + TILE_BYTES);
            }
            #pragma unroll
            for (int im = 0; im < 4; im++) {
                #pragma unroll
                for (int in = 0; in < 4; in++) {
                    const int g = in >> 1;
                    const int o = (in & 1) * 2;
                    // hi*hi + hi*lo + lo*hi, shared fp32 accumulator
                    MMA16816(acc[im][in], af[0][im], bf[0][g][o], bf[0][g][o + 1]);
                    MMA16816(acc[im][in], af[0][im], bf[1][g][o], bf[1][g][o + 1]);
                    MMA16816(acc[im][in], af[1][im], bf[0][g][o], bf[0][g][o + 1]);
                }
            }
        }
    }

    // ---- epilogue ----
    #pragma unroll
    for (int im = 0; im < 4; im++) {
        #pragma unroll
        for (int in = 0; in < 4; in++) {
            const int row = gm0 + wm0 + im * 16 + (lane >> 2);
            const int col = gn0 + wn0 + in * 8 + ((lane & 3) << 1);
            const float b0 = bias[col];
            const float b1 = bias[col + 1];
            float2 v0 = make_float2(acc[im][in][0] + b0, acc[im][in][1] + b1);
            float2 v1 = make_float2(acc[im][in][2] + b0, acc[im][in][3] + b1);
            *reinterpret_cast<float2*>(out + (size_t)row * NDIM + col) = v0;
            *reinterpret_cast<float2*>(out + (size_t)(row + 8) * NDIM + col) = v1;
        }
    }
}

extern "C" void kernel_launch(void* const* d_in, const int* in_sizes, int n_in,
                              void* d_out, int out_size) {
    const float* x    = (const float*)d_in[0];
    const float* w    = (const float*)d_in[1];
    const float* bias = (const float*)d_in[2];
    const float* mask = (const float*)d_in[3];

    const int nx4 = (MDIM * KDIM) / 4;   // 8388608
    const int nw4 = (NDIM * KDIM) / 4;   // 1048576
    split_x_kernel<<<(nx4 + 255) / 256, 256>>>((const float4*)x, nx4);
    split_w_kernel<<<(nw4 + 255) / 256, 256>>>((const float4*)w, (const float4*)mask, nw4);

    cudaFuncSetAttribute(gemm_bf16x3_kernel,
                         cudaFuncAttributeMaxDynamicSharedMemorySize, SMEM_TOTAL);
    dim3 grid(NDIM / BN, MDIM / BM);   // (16, 128)
    gemm_bf16x3_kernel<<<grid, 256, SMEM_TOTAL>>>((float*)d_out, bias);
}